// round 6
// baseline (speedup 1.0000x reference)
#include <cuda_runtime.h>
#include <math.h>

// ---- problem constants ----
#define BATCH   8
#define TT      256
#define BT      2048          // BATCH*TT
#define DM      256           // d_model
#define DI      512           // d_inner
#define DS      16            // d_state
#define DTR     16            // dt_rank

typedef unsigned long long u64;

__device__ __forceinline__ u64 pk2(float lo, float hi) {
    u64 d;
    asm("mov.b64 %0, {%1, %2};" : "=l"(d)
        : "r"(__float_as_uint(lo)), "r"(__float_as_uint(hi)));
    return d;
}
__device__ __forceinline__ u64 ffma2(u64 a, u64 b, u64 c) {
    u64 d;
    asm("fma.rn.f32x2 %0, %1, %2, %3;" : "=l"(d) : "l"(a), "l"(b), "l"(c));
    return d;
}
__device__ __forceinline__ float2 upk2(u64 v) {
    unsigned lo, hi;
    asm("mov.b64 {%0, %1}, %2;" : "=r"(lo), "=r"(hi) : "l"(v));
    return make_float2(__uint_as_float(lo), __uint_as_float(hi));
}
union F4U { float4 f; u64 u[2]; };

// ---- scratch ----
__device__ float  g_f1[2048*16*32*32];
__device__ float  g_f2[2048*32*16*16];
__device__ float  g_h [BT*DM];
__device__ float  g_xz[BT*2*DI];
__device__ float2 g_bc[BT*DS];
__device__ float2 g_du[BT*DI];
__device__ float  g_y [BT*DI];
__device__ float  g_hh[BT*64];
__device__ float  g_logits[BT];

// =====================================================================
// CNN
// =====================================================================
__global__ __launch_bounds__(512) void conv1_kernel(const float* __restrict__ x,
                             const float* __restrict__ w,
                             const float* __restrict__ b,
                             float* __restrict__ out)
{
    __shared__ float sin[65*65];
    __shared__ float sw[144];
    __shared__ float sb[16];
    int f = blockIdx.x;
    const float* xf = x + (size_t)f*4096;
    for (int i = threadIdx.x; i < 65*65; i += 512) {
        int r = i / 65, c = i - r*65;
        sin[i] = (r < 64 && c < 64) ? xf[r*64+c] : 0.f;
    }
    if (threadIdx.x < 144) sw[threadIdx.x] = w[threadIdx.x];
    if (threadIdx.x < 16)  sb[threadIdx.x] = b[threadIdx.x];
    __syncthreads();
    int xg = threadIdx.x & 3;
    int oy = (threadIdx.x >> 2) & 31;
    int cq = threadIdx.x >> 7;
    u64 acc2[4][4];
    #pragma unroll
    for (int c = 0; c < 4; c++) {
        float bb = sb[cq*4+c];
        u64 bp = pk2(bb, bb);
        #pragma unroll
        for (int p = 0; p < 4; p++) acc2[c][p] = bp;
    }
    int i0 = oy*2, j0 = xg*16;
    #pragma unroll
    for (int ky = 0; ky < 3; ky++) {
        const float* rp = sin + (i0+ky)*65 + j0;
        float r[17];
        #pragma unroll
        for (int t = 0; t < 17; t++) r[t] = rp[t];
        u64 pr[12];
        #pragma unroll
        for (int p = 0; p < 4; p++)
            #pragma unroll
            for (int l = 0; l < 3; l++)
                pr[p*3+l] = pk2(r[p*4+l], r[p*4+l+2]);
        #pragma unroll
        for (int c = 0; c < 4; c++) {
            const float* wp = sw + (cq*4+c)*9 + ky*3;
            u64 wd0 = pk2(wp[0], wp[0]);
            u64 wd1 = pk2(wp[1], wp[1]);
            u64 wd2 = pk2(wp[2], wp[2]);
            #pragma unroll
            for (int p = 0; p < 4; p++) {
                acc2[c][p] = ffma2(pr[p*3+0], wd0, acc2[c][p]);
                acc2[c][p] = ffma2(pr[p*3+1], wd1, acc2[c][p]);
                acc2[c][p] = ffma2(pr[p*3+2], wd2, acc2[c][p]);
            }
        }
    }
    #pragma unroll
    for (int c = 0; c < 4; c++)
        #pragma unroll
        for (int p = 0; p < 4; p++) {
            float2 v = upk2(acc2[c][p]);
            float2 o = make_float2(fmaxf(v.x, 0.f), fmaxf(v.y, 0.f));
            *(float2*)&out[((size_t)f*16 + cq*4+c)*1024 + oy*32 + xg*8 + 2*p] = o;
        }
}

__global__ __launch_bounds__(256) void conv2_kernel(const float* __restrict__ in,
                             const float* __restrict__ w,
                             const float* __restrict__ b,
                             float* __restrict__ out)
{
    __shared__ float sin[8*33*34];
    __shared__ float sw[2304];
    int f = blockIdx.x;
    int tid = threadIdx.x;
    int cg  = tid >> 5;
    int lane = tid & 31;
    int oy = lane >> 1;
    int xh = lane & 1;
    u64 acc2[4][4];
    #pragma unroll
    for (int c = 0; c < 4; c++) {
        float bb = __ldg(&b[cg*4+c]);
        u64 bp = pk2(bb, bb);
        #pragma unroll
        for (int p = 0; p < 4; p++) acc2[c][p] = bp;
    }
    #pragma unroll 1
    for (int pass = 0; pass < 2; pass++) {
        int ci0 = pass*8;
        __syncthreads();
        for (int idx = tid; idx < 8*33*33; idx += 256) {
            int ci = idx / 1089;
            int rem = idx - ci*1089;
            int i = rem / 33, j = rem - i*33;
            sin[ci*1122 + i*34 + j] = (i < 32 && j < 32)
                ? in[(size_t)f*16384 + (ci0+ci)*1024 + i*32 + j] : 0.f;
        }
        for (int idx = tid; idx < 2304; idx += 256) {
            int co = idx / 72;
            int rem = idx - co*72;
            int ci_l = rem / 9, k = rem - ci_l*9;
            sw[idx] = w[(co*16 + ci0 + ci_l)*9 + k];
        }
        __syncthreads();
        #pragma unroll 1
        for (int ci = 0; ci < 8; ci++) {
            const float* base = sin + ci*1122 + (2*oy)*34 + xh*16;
            #pragma unroll
            for (int row = 0; row < 3; row++) {
                const float* rp = base + row*34;
                float r[17];
                #pragma unroll
                for (int t = 0; t < 17; t++) r[t] = rp[t];
                u64 pr[12];
                #pragma unroll
                for (int p = 0; p < 4; p++)
                    #pragma unroll
                    for (int l = 0; l < 3; l++)
                        pr[p*3+l] = pk2(r[p*4+l], r[p*4+l+2]);
                #pragma unroll
                for (int c = 0; c < 4; c++) {
                    const float* wp = sw + (cg*4+c)*72 + ci*9 + row*3;
                    u64 wd0 = pk2(wp[0], wp[0]);
                    u64 wd1 = pk2(wp[1], wp[1]);
                    u64 wd2 = pk2(wp[2], wp[2]);
                    #pragma unroll
                    for (int p = 0; p < 4; p++) {
                        acc2[c][p] = ffma2(pr[p*3+0], wd0, acc2[c][p]);
                        acc2[c][p] = ffma2(pr[p*3+1], wd1, acc2[c][p]);
                        acc2[c][p] = ffma2(pr[p*3+2], wd2, acc2[c][p]);
                    }
                }
            }
        }
    }
    #pragma unroll
    for (int c = 0; c < 4; c++)
        #pragma unroll
        for (int p = 0; p < 4; p++) {
            float2 v = upk2(acc2[c][p]);
            float2 o = make_float2(fmaxf(v.x, 0.f), fmaxf(v.y, 0.f));
            *(float2*)&out[((size_t)f*32 + cg*4+c)*256 + oy*16 + xh*8 + 2*p] = o;
        }
}

// conv3 + relu + global avg pool + fc (32->256) fused; 2 frames per block
__global__ __launch_bounds__(256) void conv3poolfc_kernel(const float* __restrict__ in,
                                 const float* __restrict__ w,
                                 const float* __restrict__ b,
                                 const float* __restrict__ fcw,
                                 const float* __restrict__ fcb,
                                 float* __restrict__ h)
{
    __shared__ float sin[2*8*17*18];
    __shared__ float sw[32*8*9];
    __shared__ float zsh[64];
    int f0 = blockIdx.x * 2;
    int tid = threadIdx.x;
    int fr = tid >> 7;
    int t  = tid & 127;
    int cg = t >> 4;
    int oy = (t >> 1) & 7;
    int xh = t & 1;
    u64 acc2[4][2];
    #pragma unroll
    for (int c = 0; c < 4; c++) {
        float bb = __ldg(&b[cg*4+c]);
        u64 bp = pk2(bb, bb);
        acc2[c][0] = bp; acc2[c][1] = bp;
    }
    #pragma unroll 1
    for (int pass = 0; pass < 4; pass++) {
        int ci0 = pass*8;
        __syncthreads();
        for (int idx = tid; idx < 2*8*17*17; idx += 256) {
            int fr2 = idx / 2312;
            int rem = idx - fr2*2312;
            int ci = rem / 289;
            int r2 = rem - ci*289;
            int i = r2 / 17, j = r2 - i*17;
            sin[fr2*2448 + ci*306 + i*18 + j] = (i < 16 && j < 16)
                ? in[(size_t)(f0+fr2)*8192 + (ci0+ci)*256 + i*16 + j] : 0.f;
        }
        for (int idx = tid; idx < 2304; idx += 256) {
            int co = idx / 72;
            int rem = idx - co*72;
            int ci_l = rem / 9, k = rem - ci_l*9;
            sw[idx] = w[(co*32 + ci0 + ci_l)*9 + k];
        }
        __syncthreads();
        #pragma unroll 1
        for (int ci = 0; ci < 8; ci++) {
            const float* base = sin + fr*2448 + ci*306 + (2*oy)*18 + xh*8;
            #pragma unroll
            for (int row = 0; row < 3; row++) {
                const float* rp = base + row*18;
                float r[9];
                #pragma unroll
                for (int q = 0; q < 9; q++) r[q] = rp[q];
                u64 pr[6];
                #pragma unroll
                for (int p = 0; p < 2; p++)
                    #pragma unroll
                    for (int l = 0; l < 3; l++)
                        pr[p*3+l] = pk2(r[p*4+l], r[p*4+l+2]);
                #pragma unroll
                for (int c = 0; c < 4; c++) {
                    const float* wp = sw + (cg*4+c)*72 + ci*9 + row*3;
                    u64 wd0 = pk2(wp[0], wp[0]);
                    u64 wd1 = pk2(wp[1], wp[1]);
                    u64 wd2 = pk2(wp[2], wp[2]);
                    #pragma unroll
                    for (int p = 0; p < 2; p++) {
                        acc2[c][p] = ffma2(pr[p*3+0], wd0, acc2[c][p]);
                        acc2[c][p] = ffma2(pr[p*3+1], wd1, acc2[c][p]);
                        acc2[c][p] = ffma2(pr[p*3+2], wd2, acc2[c][p]);
                    }
                }
            }
        }
    }
    #pragma unroll
    for (int c = 0; c < 4; c++) {
        float2 v0 = upk2(acc2[c][0]), v1 = upk2(acc2[c][1]);
        float s = fmaxf(v0.x,0.f) + fmaxf(v0.y,0.f) + fmaxf(v1.x,0.f) + fmaxf(v1.y,0.f);
        #pragma unroll
        for (int o = 8; o > 0; o >>= 1) s += __shfl_down_sync(0xffffffffu, s, o, 16);
        if (oy == 0 && xh == 0) zsh[fr*32 + cg*4 + c] = s * (1.f/64.f);
    }
    __syncthreads();
    // fc: 2 frames x 256 outputs; thread -> (fr2, j) and (fr2, j+128)
    int fr2 = tid >> 7;
    int j = tid & 127;
    const float* zz = zsh + fr2*32;
    float a0 = fcb[j], a1 = fcb[j+128];
    const float4* w0p = (const float4*)(fcw + j*32);
    const float4* w1p = (const float4*)(fcw + (j+128)*32);
    #pragma unroll
    for (int k = 0; k < 8; k++) {
        float4 wv0 = w0p[k], wv1 = w1p[k];
        const float* zk = zz + k*4;
        a0 = fmaf(zk[0],wv0.x,fmaf(zk[1],wv0.y,fmaf(zk[2],wv0.z,fmaf(zk[3],wv0.w,a0))));
        a1 = fmaf(zk[0],wv1.x,fmaf(zk[1],wv1.y,fmaf(zk[2],wv1.z,fmaf(zk[3],wv1.w,a1))));
    }
    h[(size_t)(f0+fr2)*256 + j] = a0;
    h[(size_t)(f0+fr2)*256 + j + 128] = a1;
}

// =====================================================================
// Fused rmsnorm + GEMM (A rows normalized in smem), tile 64x64, K=256.
// EPI: 0 plain store, 2 bias+gelu.
// =====================================================================
#define RMS_SMEM ((256*68 + 16*68 + 256 + 256)*4)
template<int EPI>
__global__ __launch_bounds__(256) void gemm_rms_kernel(
    const float* __restrict__ H,    // [M,256]
    const float* __restrict__ NW,   // [256]
    const float* __restrict__ W,    // [N,256]
    const float* __restrict__ bias,
    float* __restrict__ C, int N)
{
    extern __shared__ float sm[];
    float* sA   = sm;               // [256][68] k-major
    float* sW   = sA + 256*68;      // [16][68]
    float* snw  = sW + 16*68;       // 256
    float* sred = snw + 256;        // 256
    int bm = blockIdx.y * 64;
    int bn = blockIdx.x * 64;
    int tid = threadIdx.x;
    snw[tid] = NW[tid];
    // load A rows raw (k-major) + partial sum of squares
    int r = tid & 63, q = tid >> 6;
    const float* hp = H + (size_t)(bm + r)*256 + q*64;
    float ss = 0.f;
    #pragma unroll
    for (int i = 0; i < 16; i++) {
        float4 v = *(const float4*)&hp[i*4];
        ss += v.x*v.x + v.y*v.y + v.z*v.z + v.w*v.w;
        int k = q*64 + i*4;
        sA[(k+0)*68 + r] = v.x;
        sA[(k+1)*68 + r] = v.y;
        sA[(k+2)*68 + r] = v.z;
        sA[(k+3)*68 + r] = v.w;
    }
    sred[q*64 + r] = ss;
    __syncthreads();
    float tot = sred[r] + sred[64+r] + sred[128+r] + sred[192+r];
    float scale = rsqrtf(tot*(1.f/256.f) + 1e-5f);
    #pragma unroll
    for (int i = 0; i < 16; i++) {
        int k = q*64 + i*4;
        #pragma unroll
        for (int c2 = 0; c2 < 4; c2++)
            sA[(k+c2)*68 + r] *= scale * snw[k+c2];
    }
    // K loop staging only W
    int tx = tid & 15, ty = tid >> 4;
    u64 acc[4][2];
    #pragma unroll
    for (int i = 0; i < 4; i++) { acc[i][0] = 0ull; acc[i][1] = 0ull; }
    for (int k0 = 0; k0 < 256; k0 += 16) {
        __syncthreads();
        {
            int rr = tid >> 2, cc = tid & 3;
            float4 u4 = *(const float4*)&W[(size_t)(bn+rr)*256 + k0 + cc*4];
            sW[(cc*4+0)*68 + rr] = u4.x;
            sW[(cc*4+1)*68 + rr] = u4.y;
            sW[(cc*4+2)*68 + rr] = u4.z;
            sW[(cc*4+3)*68 + rr] = u4.w;
        }
        __syncthreads();
        #pragma unroll
        for (int k = 0; k < 16; k++) {
            float4 a0 = *(const float4*)&sA[(k0+k)*68 + ty*4];
            F4U b0;
            b0.f = *(const float4*)&sW[k*68 + tx*4];
            u64 bp0 = b0.u[0], bp1 = b0.u[1];
            float av[4] = {a0.x, a0.y, a0.z, a0.w};
            #pragma unroll
            for (int i = 0; i < 4; i++) {
                u64 ad = pk2(av[i], av[i]);
                acc[i][0] = ffma2(ad, bp0, acc[i][0]);
                acc[i][1] = ffma2(ad, bp1, acc[i][1]);
            }
        }
    }
    #pragma unroll
    for (int i = 0; i < 4; i++) {
        int m = bm + ty*4 + i;
        float2 v0 = upk2(acc[i][0]), v1 = upk2(acc[i][1]);
        if (EPI == 0) {
            *(float4*)&C[(size_t)m*N + bn + tx*4] = make_float4(v0.x, v0.y, v1.x, v1.y);
        } else {
            float vals[4] = {v0.x, v0.y, v1.x, v1.y};
            float4 o;
            float* op = &o.x;
            #pragma unroll
            for (int j = 0; j < 4; j++) {
                float v = vals[j] + bias[bn + tx*4 + j];
                float v3 = v*v*v;
                op[j] = 0.5f * v * (1.f + tanhf(0.7978845608028654f * (v + 0.044715f*v3)));
            }
            *(float4*)&C[(size_t)m*N + bn + tx*4] = o;
        }
    }
}

// tile 32x64, 256 thr, 2x4 micro, f32x2, accumulate into C
__global__ __launch_bounds__(256) void gemm32x64_acc_kernel(const float* __restrict__ A,
                              const float* __restrict__ W,
                              float* __restrict__ C,
                              int M, int N, int K)
{
    __shared__ float As[16][36];
    __shared__ float Ws[16][68];
    int bm = blockIdx.y * 32;
    int bn = blockIdx.x * 64;
    int tid = threadIdx.x;
    int tx = tid & 15, ty = tid >> 4;
    u64 acc[2][2];
    acc[0][0]=0ull; acc[0][1]=0ull; acc[1][0]=0ull; acc[1][1]=0ull;
    for (int k0 = 0; k0 < K; k0 += 16) {
        if (tid < 128) {
            int r = tid >> 2, c = tid & 3;
            float4 v = *(const float4*)&A[(size_t)(bm+r)*K + k0 + c*4];
            As[c*4+0][r] = v.x; As[c*4+1][r] = v.y; As[c*4+2][r] = v.z; As[c*4+3][r] = v.w;
        }
        {
            int r = tid >> 2, c = tid & 3;
            float4 u = *(const float4*)&W[(size_t)(bn+r)*K + k0 + c*4];
            Ws[c*4+0][r] = u.x; Ws[c*4+1][r] = u.y; Ws[c*4+2][r] = u.z; Ws[c*4+3][r] = u.w;
        }
        __syncthreads();
        #pragma unroll
        for (int k = 0; k < 16; k++) {
            float2 a0 = *(const float2*)&As[k][ty*2];
            F4U b0;
            b0.f = *(const float4*)&Ws[k][tx*4];
            u64 bp0 = b0.u[0], bp1 = b0.u[1];
            u64 ad0 = pk2(a0.x, a0.x);
            u64 ad1 = pk2(a0.y, a0.y);
            acc[0][0] = ffma2(ad0, bp0, acc[0][0]);
            acc[0][1] = ffma2(ad0, bp1, acc[0][1]);
            acc[1][0] = ffma2(ad1, bp0, acc[1][0]);
            acc[1][1] = ffma2(ad1, bp1, acc[1][1]);
        }
        __syncthreads();
    }
    #pragma unroll
    for (int i = 0; i < 2; i++) {
        int m = bm + ty*2 + i;
        float2 v0 = upk2(acc[i][0]), v1 = upk2(acc[i][1]);
        size_t base = (size_t)m*N + bn + tx*4;
        float4 old = *(float4*)&C[base];
        old.x += v0.x; old.y += v0.y; old.z += v1.x; old.w += v1.y;
        *(float4*)&C[base] = old;
    }
}

// Fused conv1d+silu + x_proj + dt_proj: per block 16 tokens.
#define SXIDX(tok, k) ((tok)*512 + (((k) + (tok)*4) & 511))
__global__ __launch_bounds__(256) void xproj_fused_kernel(
    const float* __restrict__ xz,
    const float* __restrict__ cw,
    const float* __restrict__ cb,
    const float* __restrict__ xpw,
    const float* __restrict__ dpw,
    const float* __restrict__ dpb,
    float2* __restrict__ bc,
    float2* __restrict__ du)
{
    __shared__ float sx[16*512];
    __shared__ float buf[48*68];
    __shared__ float sdt[16*16];
    int tok0 = blockIdx.x * 16;
    int tid = threadIdx.x;

    // ---- conv1d + silu from xz into sx ----
    for (int idx = tid; idx < 2048; idx += 256) {
        int e = idx >> 2, k = idx & 3;
        buf[k*512 + e] = cw[idx];
    }
    for (int idx = tid; idx < 512; idx += 256) buf[2048 + idx] = cb[idx];
    __syncthreads();
    int tl0 = tok0 & 255;
    #pragma unroll 1
    for (int s = 0; s < 8; s++) {
        int q = tid + s*256;
        int t = q >> 7;
        int e = (q & 127)*4;
        float4 acc = *(const float4*)&buf[2048 + e];
        #pragma unroll
        for (int k = 0; k < 4; k++) {
            if (tl0 + t - 3 + k >= 0) {
                float4 xv = *(const float4*)&xz[(size_t)(tok0 + t - 3 + k)*1024 + e];
                float4 wv = *(const float4*)&buf[k*512 + e];
                acc.x = fmaf(xv.x, wv.x, acc.x);
                acc.y = fmaf(xv.y, wv.y, acc.y);
                acc.z = fmaf(xv.z, wv.z, acc.z);
                acc.w = fmaf(xv.w, wv.w, acc.w);
            }
        }
        acc.x = acc.x / (1.f + __expf(-acc.x));
        acc.y = acc.y / (1.f + __expf(-acc.y));
        acc.z = acc.z / (1.f + __expf(-acc.z));
        acc.w = acc.w / (1.f + __expf(-acc.w));
        *(float4*)&sx[SXIDX(t, e)] = acc;
    }

    // ---- Phase A: dbc = xin . xpw^T (float4 k-unroll) ----
    int tg = tid & 15;
    int jg = tid >> 4;
    int rot = tg*4;
    const float* sxr = sx + tg*512;
    float acc0 = 0.f, acc1 = 0.f, acc2 = 0.f;
    #pragma unroll 1
    for (int kc = 0; kc < 8; kc++) {
        int k0 = kc*64;
        __syncthreads();
        #pragma unroll
        for (int s = 0; s < 3; s++) {
            int q = tid + s*256;
            int r = q >> 4, c = q & 15;
            float4 v = *(const float4*)&xpw[(size_t)r*512 + k0 + c*4];
            float* dst = buf + r*68 + c*4;
            dst[0]=v.x; dst[1]=v.y; dst[2]=v.z; dst[3]=v.w;
        }
        __syncthreads();
        const float* w0 = buf + (jg*3+0)*68;
        const float* w1 = buf + (jg*3+1)*68;
        const float* w2 = buf + (jg*3+2)*68;
        #pragma unroll
        for (int k4 = 0; k4 < 16; k4++) {
            int kk = (k0 + k4*4 + rot) & 511;
            float4 xv = *(const float4*)&sxr[kk];
            float4 a4 = *(const float4*)&w0[k4*4];
            float4 b4 = *(const float4*)&w1[k4*4];
            float4 c4 = *(const float4*)&w2[k4*4];
            acc0 = fmaf(xv.x,a4.x, fmaf(xv.y,a4.y, fmaf(xv.z,a4.z, fmaf(xv.w,a4.w, acc0))));
            acc1 = fmaf(xv.x,b4.x, fmaf(xv.y,b4.y, fmaf(xv.z,b4.z, fmaf(xv.w,b4.w, acc1))));
            acc2 = fmaf(xv.x,c4.x, fmaf(xv.y,c4.y, fmaf(xv.z,c4.z, fmaf(xv.w,c4.w, acc2))));
        }
    }
    {
        float av[3] = {acc0, acc1, acc2};
        #pragma unroll
        for (int jj = 0; jj < 3; jj++) {
            int j = jg*3 + jj;
            float v = av[jj];
            int tok = tok0 + tg;
            if (j < 16)       sdt[tg*16 + j] = v;
            else if (j < 32)  bc[tok*16 + (j-16)].x = v;
            else              bc[tok*16 + (j-32)].y = v;
        }
    }

    // ---- Phase B: delta = softplus(dt . dpw^T + dpb); du = (delta, u) ----
    #pragma unroll 1
    for (int ec = 0; ec < 4; ec++) {
        int e0 = ec*128;
        __syncthreads();
        #pragma unroll
        for (int s = 0; s < 2; s++) {
            int q = tid + s*256;
            int r = q >> 2, c = q & 3;
            float4 v = *(const float4*)&dpw[(size_t)(e0+r)*16 + c*4];
            float* dst = buf + r*16 + c*4;
            dst[0]=v.x; dst[1]=v.y; dst[2]=v.z; dst[3]=v.w;
        }
        __syncthreads();
        #pragma unroll 1
        for (int s = 0; s < 8; s++) {
            int idx = tid + s*256;
            int e_l = idx & 127;
            int tok = idx >> 7;
            int e = e0 + e_l;
            const float* dr = sdt + tok*16;
            const float* wr = buf + e_l*16;
            float a = dpb[e];
            #pragma unroll
            for (int k = 0; k < 16; k++) a = fmaf(dr[k], wr[k], a);
            float sp = (a > 20.f) ? a : log1pf(expf(a));
            float u = sx[SXIDX(tok, e)];
            du[(size_t)(tok0+tok)*512 + e] = make_float2(sp, u);
        }
    }
}

// Selective scan: chunked register prefetch + pipelined shfl reduction
__global__ __launch_bounds__(256) void scan_kernel(const float2* __restrict__ du,
                            const float* __restrict__ xz,
                            const float2* __restrict__ bc,
                            const float* __restrict__ A_log,
                            const float* __restrict__ Dp,
                            float* __restrict__ yout)
{
    int tid = blockIdx.x * blockDim.x + threadIdx.x;
    int ch = tid >> 4;
    int n = tid & 15;
    int b = ch >> 9;
    int e = ch & 511;
    float A  = -expf(A_log[e*16 + n]);
    float Dv = Dp[e];
    const float2* duP = du + (size_t)(b*256)*512 + e;
    const float2* bcP = bc + (size_t)(b*256)*16 + n;
    const float*  zP  = xz + (size_t)(b*256)*1024 + 512 + e;
    float* yP = yout + (size_t)(b*256)*512 + e;

    float2 dv[2][8], bv[2][8];
    float  zv[2][8];
    #pragma unroll
    for (int i = 0; i < 8; i++) {
        dv[0][i] = duP[i*512];
        bv[0][i] = bcP[i*16];
    }
    if (n == 0) {
        #pragma unroll
        for (int i = 0; i < 8; i++) zv[0][i] = zP[i*1024];
    }
    float h = 0.f;
    int buf = 0;
    #pragma unroll 1
    for (int c = 0; c < 32; c++) {
        int nb = buf ^ 1;
        if (c < 31) {
            int t1 = c*8 + 8;
            #pragma unroll
            for (int i = 0; i < 8; i++) {
                dv[nb][i] = duP[(t1+i)*512];
                bv[nb][i] = bcP[(t1+i)*16];
            }
            if (n == 0) {
                #pragma unroll
                for (int i = 0; i < 8; i++) zv[nb][i] = zP[(size_t)(t1+i)*1024];
            }
        }
        float part[8];
        #pragma unroll
        for (int i = 0; i < 8; i++) {
            float2 duv = dv[buf][i];
            float2 bcv = bv[buf][i];
            float dA = __expf(duv.x * A);
            h = fmaf(h, dA, duv.x * bcv.x * duv.y);
            part[i] = h * bcv.y;
        }
        #pragma unroll
        for (int o = 8; o > 0; o >>= 1) {
            #pragma unroll
            for (int i = 0; i < 8; i++)
                part[i] += __shfl_down_sync(0xffffffffu, part[i], o, 16);
        }
        if (n == 0) {
            #pragma unroll
            for (int i = 0; i < 8; i++) {
                float z = zv[buf][i];
                float yy = part[i] + dv[buf][i].y * Dv;
                yP[(size_t)(c*8+i)*512] = yy * (z / (1.f + __expf(-z)));
            }
        }
        buf = nb;
    }
}

// =====================================================================
// Head tail
// =====================================================================
__global__ __launch_bounds__(256) void head2_kernel(const float* __restrict__ hh,
                             const float* __restrict__ w,
                             const float* __restrict__ b,
                             float* __restrict__ logits)
{
    int wid = (blockIdx.x * blockDim.x + threadIdx.x) >> 5;
    int lane = threadIdx.x & 31;
    const float* xr = hh + (size_t)wid*64;
    float acc = fmaf(xr[lane], w[lane], xr[lane+32]*w[lane+32]);
    #pragma unroll
    for (int o = 16; o > 0; o >>= 1) acc += __shfl_down_sync(0xffffffffu, acc, o);
    if (lane == 0) logits[wid] = acc + b[0];
}

__global__ __launch_bounds__(256) void softmax_kernel(const float* __restrict__ logits,
                               float* __restrict__ out)
{
    int b = blockIdx.x;
    int t = threadIdx.x;
    float v = logits[b*256 + t];
    __shared__ float red[8];
    __shared__ float sM, sS;
    float m = v;
    #pragma unroll
    for (int o = 16; o > 0; o >>= 1) m = fmaxf(m, __shfl_xor_sync(0xffffffffu, m, o));
    if ((t & 31) == 0) red[t >> 5] = m;
    __syncthreads();
    if (t < 8) {
        float mm = red[t];
        #pragma unroll
        for (int o = 4; o > 0; o >>= 1) mm = fmaxf(mm, __shfl_xor_sync(0xffu, mm, o, 8));
        if (t == 0) sM = mm;
    }
    __syncthreads();
    float e = expf(v - sM);
    float s = e;
    #pragma unroll
    for (int o = 16; o > 0; o >>= 1) s += __shfl_xor_sync(0xffffffffu, s, o);
    __syncthreads();
    if ((t & 31) == 0) red[t >> 5] = s;
    __syncthreads();
    if (t < 8) {
        float ss2 = red[t];
        #pragma unroll
        for (int o = 4; o > 0; o >>= 1) ss2 += __shfl_xor_sync(0xffu, ss2, o, 8);
        if (t == 0) sS = ss2;
    }
    __syncthreads();
    out[b*256 + t] = (t == 0) ? 0.f : e / sS;
}

// =====================================================================
// Launcher
// =====================================================================
extern "C" void kernel_launch(void* const* d_in, const int* in_sizes, int n_in,
                              void* d_out, int out_size)
{
    (void)in_sizes; (void)n_in; (void)out_size;
    const float* x        = (const float*)d_in[0];
    const float* cnn_w1   = (const float*)d_in[1];
    const float* cnn_b1   = (const float*)d_in[2];
    const float* cnn_w2   = (const float*)d_in[3];
    const float* cnn_b2   = (const float*)d_in[4];
    const float* cnn_w3   = (const float*)d_in[5];
    const float* cnn_b3   = (const float*)d_in[6];
    const float* fc_w     = (const float*)d_in[7];
    const float* fc_b     = (const float*)d_in[8];
    const float* norm_w   = (const float*)d_in[9];
    const float* in_proj_w= (const float*)d_in[10];
    const float* conv1d_w = (const float*)d_in[11];
    const float* conv1d_b = (const float*)d_in[12];
    const float* x_proj_w = (const float*)d_in[13];
    const float* dt_proj_w= (const float*)d_in[14];
    const float* dt_proj_b= (const float*)d_in[15];
    const float* A_log    = (const float*)d_in[16];
    const float* Dp       = (const float*)d_in[17];
    const float* out_proj_w=(const float*)d_in[18];
    const float* norm_f_w = (const float*)d_in[19];
    const float* head_w1  = (const float*)d_in[20];
    const float* head_b1  = (const float*)d_in[21];
    const float* head_w2  = (const float*)d_in[22];
    const float* head_b2  = (const float*)d_in[23];
    float* out = (float*)d_out;

    float *f1, *f2, *h, *xz, *y, *hh, *logits;
    float2 *bc, *du;
    cudaGetSymbolAddress((void**)&f1, g_f1);
    cudaGetSymbolAddress((void**)&f2, g_f2);
    cudaGetSymbolAddress((void**)&h,  g_h);
    cudaGetSymbolAddress((void**)&xz, g_xz);
    cudaGetSymbolAddress((void**)&bc, g_bc);
    cudaGetSymbolAddress((void**)&du, g_du);
    cudaGetSymbolAddress((void**)&y,  g_y);
    cudaGetSymbolAddress((void**)&hh, g_hh);
    cudaGetSymbolAddress((void**)&logits, g_logits);

    cudaFuncSetAttribute(gemm_rms_kernel<0>,
        cudaFuncAttributeMaxDynamicSharedMemorySize, RMS_SMEM);
    cudaFuncSetAttribute(gemm_rms_kernel<2>,
        cudaFuncAttributeMaxDynamicSharedMemorySize, RMS_SMEM);

    // --- CNN encoder ---
    conv1_kernel<<<2048, 512>>>(x, cnn_w1, cnn_b1, f1);
    conv2_kernel<<<2048, 256>>>(f1, cnn_w2, cnn_b2, f2);
    conv3poolfc_kernel<<<1024, 256>>>(f2, cnn_w3, cnn_b3, fc_w, fc_b, h);

    // --- Mamba layers ---
    for (int l = 0; l < 6; l++) {
        const float* nw  = norm_w     + (size_t)l*DM;
        const float* ipw = in_proj_w  + (size_t)l*2*DI*DM;
        const float* cw  = conv1d_w   + (size_t)l*DI*4;
        const float* cb  = conv1d_b   + (size_t)l*DI;
        const float* xpw = x_proj_w   + (size_t)l*48*DI;
        const float* dpw = dt_proj_w  + (size_t)l*DI*DTR;
        const float* dpb = dt_proj_b  + (size_t)l*DI;
        const float* al  = A_log      + (size_t)l*DI*DS;
        const float* dv  = Dp         + (size_t)l*DI;
        const float* opw = out_proj_w + (size_t)l*DM*DI;

        gemm_rms_kernel<0><<<dim3(16, 32), 256, RMS_SMEM>>>(h, nw, ipw, nullptr, xz, 1024);
        xproj_fused_kernel<<<128, 256>>>(xz, cw, cb, xpw, dpw, dpb, bc, du);
        scan_kernel<<<BATCH*DI*DS/256, 256>>>(du, xz, bc, al, dv, y);
        gemm32x64_acc_kernel<<<dim3(4, 64), 256>>>(y, opw, h, BT, 256, 512);
    }

    // --- Head ---
    gemm_rms_kernel<2><<<dim3(1, 32), 256, RMS_SMEM>>>(h, norm_f_w, head_w1, head_b1, hh, 64);
    head2_kernel<<<BT*32/256, 256>>>(hh, head_w2, head_b2, logits);
    softmax_kernel<<<BATCH, 256>>>(logits, out);
}

// round 7
// speedup vs baseline: 1.0937x; 1.0937x over previous
#include <cuda_runtime.h>
#include <math.h>

// ---- problem constants ----
#define BATCH   8
#define TT      256
#define BT      2048          // BATCH*TT
#define DM      256           // d_model
#define DI      512           // d_inner
#define DS      16            // d_state
#define DTR     16            // dt_rank

typedef unsigned long long u64;

__device__ __forceinline__ u64 pk2(float lo, float hi) {
    u64 d;
    asm("mov.b64 %0, {%1, %2};" : "=l"(d)
        : "r"(__float_as_uint(lo)), "r"(__float_as_uint(hi)));
    return d;
}
__device__ __forceinline__ u64 ffma2(u64 a, u64 b, u64 c) {
    u64 d;
    asm("fma.rn.f32x2 %0, %1, %2, %3;" : "=l"(d) : "l"(a), "l"(b), "l"(c));
    return d;
}
__device__ __forceinline__ float2 upk2(u64 v) {
    unsigned lo, hi;
    asm("mov.b64 {%0, %1}, %2;" : "=r"(lo), "=r"(hi) : "l"(v));
    return make_float2(__uint_as_float(lo), __uint_as_float(hi));
}
union F4U { float4 f; u64 u[2]; };

// ---- scratch ----
__device__ float  g_f1[2048*16*32*32];
__device__ float  g_f2[2048*32*16*16];
__device__ float  g_h [BT*DM];
__device__ float  g_xn[BT*DM];
__device__ float  g_xz[BT*2*DI];
__device__ float2 g_bc[BT*DS];
__device__ float2 g_du[BT*DI];
__device__ float  g_y [BT*DI];
__device__ float  g_hh[BT*64];
__device__ float  g_logits[BT];

// =====================================================================
// CNN
// =====================================================================
__global__ __launch_bounds__(512) void conv1_kernel(const float* __restrict__ x,
                             const float* __restrict__ w,
                             const float* __restrict__ b,
                             float* __restrict__ out)
{
    __shared__ float sin[65*65];
    __shared__ float sw[144];
    __shared__ float sb[16];
    int f = blockIdx.x;
    const float* xf = x + (size_t)f*4096;
    for (int i = threadIdx.x; i < 65*65; i += 512) {
        int r = i / 65, c = i - r*65;
        sin[i] = (r < 64 && c < 64) ? xf[r*64+c] : 0.f;
    }
    if (threadIdx.x < 144) sw[threadIdx.x] = w[threadIdx.x];
    if (threadIdx.x < 16)  sb[threadIdx.x] = b[threadIdx.x];
    __syncthreads();
    int xg = threadIdx.x & 3;
    int oy = (threadIdx.x >> 2) & 31;
    int cq = threadIdx.x >> 7;
    u64 acc2[4][4];
    #pragma unroll
    for (int c = 0; c < 4; c++) {
        float bb = sb[cq*4+c];
        u64 bp = pk2(bb, bb);
        #pragma unroll
        for (int p = 0; p < 4; p++) acc2[c][p] = bp;
    }
    int i0 = oy*2, j0 = xg*16;
    #pragma unroll
    for (int ky = 0; ky < 3; ky++) {
        const float* rp = sin + (i0+ky)*65 + j0;
        float r[17];
        #pragma unroll
        for (int t = 0; t < 17; t++) r[t] = rp[t];
        u64 pr[12];
        #pragma unroll
        for (int p = 0; p < 4; p++)
            #pragma unroll
            for (int l = 0; l < 3; l++)
                pr[p*3+l] = pk2(r[p*4+l], r[p*4+l+2]);
        #pragma unroll
        for (int c = 0; c < 4; c++) {
            const float* wp = sw + (cq*4+c)*9 + ky*3;
            u64 wd0 = pk2(wp[0], wp[0]);
            u64 wd1 = pk2(wp[1], wp[1]);
            u64 wd2 = pk2(wp[2], wp[2]);
            #pragma unroll
            for (int p = 0; p < 4; p++) {
                acc2[c][p] = ffma2(pr[p*3+0], wd0, acc2[c][p]);
                acc2[c][p] = ffma2(pr[p*3+1], wd1, acc2[c][p]);
                acc2[c][p] = ffma2(pr[p*3+2], wd2, acc2[c][p]);
            }
        }
    }
    #pragma unroll
    for (int c = 0; c < 4; c++)
        #pragma unroll
        for (int p = 0; p < 4; p++) {
            float2 v = upk2(acc2[c][p]);
            float2 o = make_float2(fmaxf(v.x, 0.f), fmaxf(v.y, 0.f));
            *(float2*)&out[((size_t)f*16 + cq*4+c)*1024 + oy*32 + xg*8 + 2*p] = o;
        }
}

__global__ __launch_bounds__(256) void conv2_kernel(const float* __restrict__ in,
                             const float* __restrict__ w,
                             const float* __restrict__ b,
                             float* __restrict__ out)
{
    __shared__ float sin[8*33*34];
    __shared__ float sw[2304];
    int f = blockIdx.x;
    int tid = threadIdx.x;
    int cg  = tid >> 5;
    int lane = tid & 31;
    int oy = lane >> 1;
    int xh = lane & 1;
    u64 acc2[4][4];
    #pragma unroll
    for (int c = 0; c < 4; c++) {
        float bb = __ldg(&b[cg*4+c]);
        u64 bp = pk2(bb, bb);
        #pragma unroll
        for (int p = 0; p < 4; p++) acc2[c][p] = bp;
    }
    #pragma unroll 1
    for (int pass = 0; pass < 2; pass++) {
        int ci0 = pass*8;
        __syncthreads();
        for (int idx = tid; idx < 8*33*33; idx += 256) {
            int ci = idx / 1089;
            int rem = idx - ci*1089;
            int i = rem / 33, j = rem - i*33;
            sin[ci*1122 + i*34 + j] = (i < 32 && j < 32)
                ? in[(size_t)f*16384 + (ci0+ci)*1024 + i*32 + j] : 0.f;
        }
        for (int idx = tid; idx < 2304; idx += 256) {
            int co = idx / 72;
            int rem = idx - co*72;
            int ci_l = rem / 9, k = rem - ci_l*9;
            sw[idx] = w[(co*16 + ci0 + ci_l)*9 + k];
        }
        __syncthreads();
        #pragma unroll 1
        for (int ci = 0; ci < 8; ci++) {
            const float* base = sin + ci*1122 + (2*oy)*34 + xh*16;
            #pragma unroll
            for (int row = 0; row < 3; row++) {
                const float* rp = base + row*34;
                float r[17];
                #pragma unroll
                for (int t = 0; t < 17; t++) r[t] = rp[t];
                u64 pr[12];
                #pragma unroll
                for (int p = 0; p < 4; p++)
                    #pragma unroll
                    for (int l = 0; l < 3; l++)
                        pr[p*3+l] = pk2(r[p*4+l], r[p*4+l+2]);
                #pragma unroll
                for (int c = 0; c < 4; c++) {
                    const float* wp = sw + (cg*4+c)*72 + ci*9 + row*3;
                    u64 wd0 = pk2(wp[0], wp[0]);
                    u64 wd1 = pk2(wp[1], wp[1]);
                    u64 wd2 = pk2(wp[2], wp[2]);
                    #pragma unroll
                    for (int p = 0; p < 4; p++) {
                        acc2[c][p] = ffma2(pr[p*3+0], wd0, acc2[c][p]);
                        acc2[c][p] = ffma2(pr[p*3+1], wd1, acc2[c][p]);
                        acc2[c][p] = ffma2(pr[p*3+2], wd2, acc2[c][p]);
                    }
                }
            }
        }
    }
    #pragma unroll
    for (int c = 0; c < 4; c++)
        #pragma unroll
        for (int p = 0; p < 4; p++) {
            float2 v = upk2(acc2[c][p]);
            float2 o = make_float2(fmaxf(v.x, 0.f), fmaxf(v.y, 0.f));
            *(float2*)&out[((size_t)f*32 + cg*4+c)*256 + oy*16 + xh*8 + 2*p] = o;
        }
}

// conv3 + relu + global avg pool + fc (32->256) fused; 2 frames per block
__global__ __launch_bounds__(256) void conv3poolfc_kernel(const float* __restrict__ in,
                                 const float* __restrict__ w,
                                 const float* __restrict__ b,
                                 const float* __restrict__ fcw,
                                 const float* __restrict__ fcb,
                                 float* __restrict__ h)
{
    __shared__ float sin[2*8*17*18];
    __shared__ float sw[32*8*9];
    __shared__ float zsh[64];
    int f0 = blockIdx.x * 2;
    int tid = threadIdx.x;
    int fr = tid >> 7;
    int t  = tid & 127;
    int cg = t >> 4;
    int oy = (t >> 1) & 7;
    int xh = t & 1;
    u64 acc2[4][2];
    #pragma unroll
    for (int c = 0; c < 4; c++) {
        float bb = __ldg(&b[cg*4+c]);
        u64 bp = pk2(bb, bb);
        acc2[c][0] = bp; acc2[c][1] = bp;
    }
    #pragma unroll 1
    for (int pass = 0; pass < 4; pass++) {
        int ci0 = pass*8;
        __syncthreads();
        for (int idx = tid; idx < 2*8*17*17; idx += 256) {
            int fr2 = idx / 2312;
            int rem = idx - fr2*2312;
            int ci = rem / 289;
            int r2 = rem - ci*289;
            int i = r2 / 17, j = r2 - i*17;
            sin[fr2*2448 + ci*306 + i*18 + j] = (i < 16 && j < 16)
                ? in[(size_t)(f0+fr2)*8192 + (ci0+ci)*256 + i*16 + j] : 0.f;
        }
        for (int idx = tid; idx < 2304; idx += 256) {
            int co = idx / 72;
            int rem = idx - co*72;
            int ci_l = rem / 9, k = rem - ci_l*9;
            sw[idx] = w[(co*32 + ci0 + ci_l)*9 + k];
        }
        __syncthreads();
        #pragma unroll 1
        for (int ci = 0; ci < 8; ci++) {
            const float* base = sin + fr*2448 + ci*306 + (2*oy)*18 + xh*8;
            #pragma unroll
            for (int row = 0; row < 3; row++) {
                const float* rp = base + row*18;
                float r[9];
                #pragma unroll
                for (int q = 0; q < 9; q++) r[q] = rp[q];
                u64 pr[6];
                #pragma unroll
                for (int p = 0; p < 2; p++)
                    #pragma unroll
                    for (int l = 0; l < 3; l++)
                        pr[p*3+l] = pk2(r[p*4+l], r[p*4+l+2]);
                #pragma unroll
                for (int c = 0; c < 4; c++) {
                    const float* wp = sw + (cg*4+c)*72 + ci*9 + row*3;
                    u64 wd0 = pk2(wp[0], wp[0]);
                    u64 wd1 = pk2(wp[1], wp[1]);
                    u64 wd2 = pk2(wp[2], wp[2]);
                    #pragma unroll
                    for (int p = 0; p < 2; p++) {
                        acc2[c][p] = ffma2(pr[p*3+0], wd0, acc2[c][p]);
                        acc2[c][p] = ffma2(pr[p*3+1], wd1, acc2[c][p]);
                        acc2[c][p] = ffma2(pr[p*3+2], wd2, acc2[c][p]);
                    }
                }
            }
        }
    }
    #pragma unroll
    for (int c = 0; c < 4; c++) {
        float2 v0 = upk2(acc2[c][0]), v1 = upk2(acc2[c][1]);
        float s = fmaxf(v0.x,0.f) + fmaxf(v0.y,0.f) + fmaxf(v1.x,0.f) + fmaxf(v1.y,0.f);
        #pragma unroll
        for (int o = 8; o > 0; o >>= 1) s += __shfl_down_sync(0xffffffffu, s, o, 16);
        if (oy == 0 && xh == 0) zsh[fr*32 + cg*4 + c] = s * (1.f/64.f);
    }
    __syncthreads();
    int fr2 = tid >> 7;
    int j = tid & 127;
    const float* zz = zsh + fr2*32;
    float a0 = fcb[j], a1 = fcb[j+128];
    const float4* w0p = (const float4*)(fcw + j*32);
    const float4* w1p = (const float4*)(fcw + (j+128)*32);
    #pragma unroll
    for (int k = 0; k < 8; k++) {
        float4 wv0 = w0p[k], wv1 = w1p[k];
        const float* zk = zz + k*4;
        a0 = fmaf(zk[0],wv0.x,fmaf(zk[1],wv0.y,fmaf(zk[2],wv0.z,fmaf(zk[3],wv0.w,a0))));
        a1 = fmaf(zk[0],wv1.x,fmaf(zk[1],wv1.y,fmaf(zk[2],wv1.z,fmaf(zk[3],wv1.w,a1))));
    }
    h[(size_t)(f0+fr2)*256 + j] = a0;
    h[(size_t)(f0+fr2)*256 + j + 128] = a1;
}

// =====================================================================
// Mamba pieces
// =====================================================================
__global__ __launch_bounds__(256) void rmsnorm_kernel(const float* __restrict__ x,
                               const float* __restrict__ w,
                               float* __restrict__ out)
{
    int tok = blockIdx.x*8 + (threadIdx.x >> 5);
    int lane = threadIdx.x & 31;
    const float4* xr = (const float4*)(x + (size_t)tok*256);
    float4 v0 = xr[lane*2], v1 = xr[lane*2+1];
    float ss = v0.x*v0.x + v0.y*v0.y + v0.z*v0.z + v0.w*v0.w
             + v1.x*v1.x + v1.y*v1.y + v1.z*v1.z + v1.w*v1.w;
    #pragma unroll
    for (int o = 16; o > 0; o >>= 1) ss += __shfl_xor_sync(0xffffffffu, ss, o);
    float scale = rsqrtf(ss * (1.f/256.f) + 1e-5f);
    const float4* wr = (const float4*)w;
    float4 w0 = wr[lane*2], w1 = wr[lane*2+1];
    float4 o0, o1;
    o0.x = v0.x*scale*w0.x; o0.y = v0.y*scale*w0.y; o0.z = v0.z*scale*w0.z; o0.w = v0.w*scale*w0.w;
    o1.x = v1.x*scale*w1.x; o1.y = v1.y*scale*w1.y; o1.z = v1.z*scale*w1.z; o1.w = v1.w*scale*w1.w;
    float4* outr = (float4*)(out + (size_t)tok*256);
    outr[lane*2] = o0; outr[lane*2+1] = o1;
}

// tile 64x64, 256 thr, 4x4 micro, f32x2, global-load prefetch
__global__ __launch_bounds__(256) void gemm64_kernel(const float* __restrict__ A,
                              const float* __restrict__ W,
                              float* __restrict__ C,
                              int M, int N, int K)
{
    __shared__ float As[16][68];
    __shared__ float Ws[16][68];
    int bm = blockIdx.y * 64;
    int bn = blockIdx.x * 64;
    int tid = threadIdx.x;
    int tx = tid & 15, ty = tid >> 4;
    int r = tid >> 2, c = tid & 3;
    const float* Ap = &A[(size_t)(bm+r)*K + c*4];
    const float* Wp = &W[(size_t)(bn+r)*K + c*4];
    float4 va = *(const float4*)Ap;
    float4 vw = *(const float4*)Wp;
    u64 acc[4][2];
    #pragma unroll
    for (int i = 0; i < 4; i++) { acc[i][0] = 0ull; acc[i][1] = 0ull; }
    for (int k0 = 0; k0 < K; k0 += 16) {
        As[c*4+0][r] = va.x; As[c*4+1][r] = va.y; As[c*4+2][r] = va.z; As[c*4+3][r] = va.w;
        Ws[c*4+0][r] = vw.x; Ws[c*4+1][r] = vw.y; Ws[c*4+2][r] = vw.z; Ws[c*4+3][r] = vw.w;
        __syncthreads();
        if (k0 + 16 < K) {
            va = *(const float4*)(Ap + k0 + 16);
            vw = *(const float4*)(Wp + k0 + 16);
        }
        #pragma unroll
        for (int k = 0; k < 16; k++) {
            float4 a0 = *(const float4*)&As[k][ty*4];
            F4U b0;
            b0.f = *(const float4*)&Ws[k][tx*4];
            u64 bp0 = b0.u[0], bp1 = b0.u[1];
            float av[4] = {a0.x, a0.y, a0.z, a0.w};
            #pragma unroll
            for (int i = 0; i < 4; i++) {
                u64 ad = pk2(av[i], av[i]);
                acc[i][0] = ffma2(ad, bp0, acc[i][0]);
                acc[i][1] = ffma2(ad, bp1, acc[i][1]);
            }
        }
        __syncthreads();
    }
    #pragma unroll
    for (int i = 0; i < 4; i++) {
        int m = bm + ty*4 + i;
        float2 v0 = upk2(acc[i][0]), v1 = upk2(acc[i][1]);
        *(float4*)&C[(size_t)m*N + bn + tx*4] = make_float4(v0.x, v0.y, v1.x, v1.y);
    }
}

// tile 32x64, 256 thr, 2x4 micro, f32x2, prefetch. EPI: 1 accumulate, 2 bias+gelu
template<int EPI>
__global__ __launch_bounds__(256) void gemm32x64_kernel(const float* __restrict__ A,
                              const float* __restrict__ W,
                              const float* __restrict__ bias,
                              float* __restrict__ C,
                              int M, int N, int K)
{
    __shared__ float As[16][36];
    __shared__ float Ws[16][68];
    int bm = blockIdx.y * 32;
    int bn = blockIdx.x * 64;
    int tid = threadIdx.x;
    int tx = tid & 15, ty = tid >> 4;
    int r = tid >> 2, c = tid & 3;
    const float* Ap = &A[(size_t)(bm+r)*K + c*4];
    const float* Wp = &W[(size_t)(bn+r)*K + c*4];
    float4 va;
    if (tid < 128) va = *(const float4*)Ap;
    float4 vw = *(const float4*)Wp;
    u64 acc[2][2];
    acc[0][0]=0ull; acc[0][1]=0ull; acc[1][0]=0ull; acc[1][1]=0ull;
    for (int k0 = 0; k0 < K; k0 += 16) {
        if (tid < 128) {
            As[c*4+0][r] = va.x; As[c*4+1][r] = va.y; As[c*4+2][r] = va.z; As[c*4+3][r] = va.w;
        }
        Ws[c*4+0][r] = vw.x; Ws[c*4+1][r] = vw.y; Ws[c*4+2][r] = vw.z; Ws[c*4+3][r] = vw.w;
        __syncthreads();
        if (k0 + 16 < K) {
            if (tid < 128) va = *(const float4*)(Ap + k0 + 16);
            vw = *(const float4*)(Wp + k0 + 16);
        }
        #pragma unroll
        for (int k = 0; k < 16; k++) {
            float2 a0 = *(const float2*)&As[k][ty*2];
            F4U b0;
            b0.f = *(const float4*)&Ws[k][tx*4];
            u64 bp0 = b0.u[0], bp1 = b0.u[1];
            u64 ad0 = pk2(a0.x, a0.x);
            u64 ad1 = pk2(a0.y, a0.y);
            acc[0][0] = ffma2(ad0, bp0, acc[0][0]);
            acc[0][1] = ffma2(ad0, bp1, acc[0][1]);
            acc[1][0] = ffma2(ad1, bp0, acc[1][0]);
            acc[1][1] = ffma2(ad1, bp1, acc[1][1]);
        }
        __syncthreads();
    }
    #pragma unroll
    for (int i = 0; i < 2; i++) {
        int m = bm + ty*2 + i;
        float2 v0 = upk2(acc[i][0]), v1 = upk2(acc[i][1]);
        float vals[4] = {v0.x, v0.y, v1.x, v1.y};
        size_t base = (size_t)m*N + bn + tx*4;
        if (EPI == 1) {
            float4 old = *(float4*)&C[base];
            old.x += vals[0]; old.y += vals[1]; old.z += vals[2]; old.w += vals[3];
            *(float4*)&C[base] = old;
        } else {
            float4 o;
            float* op = &o.x;
            #pragma unroll
            for (int j = 0; j < 4; j++) {
                float v = vals[j] + bias[bn + tx*4 + j];
                float v3 = v*v*v;
                op[j] = 0.5f * v * (1.f + tanhf(0.7978845608028654f * (v + 0.044715f*v3)));
            }
            *(float4*)&C[base] = o;
        }
    }
}

// Fused conv1d+silu + x_proj + dt_proj: per block 16 tokens.
#define SXIDX(tok, k) ((tok)*512 + (((k) + (tok)*4) & 511))
__global__ __launch_bounds__(256) void xproj_fused_kernel(
    const float* __restrict__ xz,
    const float* __restrict__ cw,
    const float* __restrict__ cb,
    const float* __restrict__ xpw,
    const float* __restrict__ dpw,
    const float* __restrict__ dpb,
    float2* __restrict__ bc,
    float2* __restrict__ du)
{
    __shared__ float sx[16*512];
    __shared__ float buf[48*68];
    __shared__ float sdt[16*16];
    int tok0 = blockIdx.x * 16;
    int tid = threadIdx.x;

    // ---- conv1d + silu from xz into sx ----
    for (int idx = tid; idx < 2048; idx += 256) {
        int e = idx >> 2, k = idx & 3;
        buf[k*512 + e] = cw[idx];
    }
    for (int idx = tid; idx < 512; idx += 256) buf[2048 + idx] = cb[idx];
    __syncthreads();
    int tl0 = tok0 & 255;
    #pragma unroll 1
    for (int s = 0; s < 8; s++) {
        int q = tid + s*256;
        int t = q >> 7;
        int e = (q & 127)*4;
        float4 acc = *(const float4*)&buf[2048 + e];
        #pragma unroll
        for (int k = 0; k < 4; k++) {
            if (tl0 + t - 3 + k >= 0) {
                float4 xv = *(const float4*)&xz[(size_t)(tok0 + t - 3 + k)*1024 + e];
                float4 wv = *(const float4*)&buf[k*512 + e];
                acc.x = fmaf(xv.x, wv.x, acc.x);
                acc.y = fmaf(xv.y, wv.y, acc.y);
                acc.z = fmaf(xv.z, wv.z, acc.z);
                acc.w = fmaf(xv.w, wv.w, acc.w);
            }
        }
        acc.x = acc.x / (1.f + __expf(-acc.x));
        acc.y = acc.y / (1.f + __expf(-acc.y));
        acc.z = acc.z / (1.f + __expf(-acc.z));
        acc.w = acc.w / (1.f + __expf(-acc.w));
        *(float4*)&sx[SXIDX(t, e)] = acc;
    }

    // ---- Phase A: dbc = xin . xpw^T (float4 k-unroll) ----
    int tg = tid & 15;
    int jg = tid >> 4;
    int rot = tg*4;
    const float* sxr = sx + tg*512;
    float acc0 = 0.f, acc1 = 0.f, acc2 = 0.f;
    #pragma unroll 1
    for (int kc = 0; kc < 8; kc++) {
        int k0 = kc*64;
        __syncthreads();
        #pragma unroll
        for (int s = 0; s < 3; s++) {
            int q = tid + s*256;
            int r = q >> 4, c = q & 15;
            float4 v = *(const float4*)&xpw[(size_t)r*512 + k0 + c*4];
            float* dst = buf + r*68 + c*4;
            dst[0]=v.x; dst[1]=v.y; dst[2]=v.z; dst[3]=v.w;
        }
        __syncthreads();
        const float* w0 = buf + (jg*3+0)*68;
        const float* w1 = buf + (jg*3+1)*68;
        const float* w2 = buf + (jg*3+2)*68;
        #pragma unroll
        for (int k4 = 0; k4 < 16; k4++) {
            int kk = (k0 + k4*4 + rot) & 511;
            float4 xv = *(const float4*)&sxr[kk];
            float4 a4 = *(const float4*)&w0[k4*4];
            float4 b4 = *(const float4*)&w1[k4*4];
            float4 c4 = *(const float4*)&w2[k4*4];
            acc0 = fmaf(xv.x,a4.x, fmaf(xv.y,a4.y, fmaf(xv.z,a4.z, fmaf(xv.w,a4.w, acc0))));
            acc1 = fmaf(xv.x,b4.x, fmaf(xv.y,b4.y, fmaf(xv.z,b4.z, fmaf(xv.w,b4.w, acc1))));
            acc2 = fmaf(xv.x,c4.x, fmaf(xv.y,c4.y, fmaf(xv.z,c4.z, fmaf(xv.w,c4.w, acc2))));
        }
    }
    {
        float av[3] = {acc0, acc1, acc2};
        #pragma unroll
        for (int jj = 0; jj < 3; jj++) {
            int j = jg*3 + jj;
            float v = av[jj];
            int tok = tok0 + tg;
            if (j < 16)       sdt[tg*16 + j] = v;
            else if (j < 32)  bc[tok*16 + (j-16)].x = v;
            else              bc[tok*16 + (j-32)].y = v;
        }
    }

    // ---- Phase B: delta = softplus(dt . dpw^T + dpb); du = (delta, u) ----
    #pragma unroll 1
    for (int ec = 0; ec < 4; ec++) {
        int e0 = ec*128;
        __syncthreads();
        #pragma unroll
        for (int s = 0; s < 2; s++) {
            int q = tid + s*256;
            int r = q >> 2, c = q & 3;
            float4 v = *(const float4*)&dpw[(size_t)(e0+r)*16 + c*4];
            float* dst = buf + r*16 + c*4;
            dst[0]=v.x; dst[1]=v.y; dst[2]=v.z; dst[3]=v.w;
        }
        __syncthreads();
        #pragma unroll 1
        for (int s = 0; s < 8; s++) {
            int idx = tid + s*256;
            int e_l = idx & 127;
            int tok = idx >> 7;
            int e = e0 + e_l;
            const float* dr = sdt + tok*16;
            const float* wr = buf + e_l*16;
            float a = dpb[e];
            #pragma unroll
            for (int k = 0; k < 16; k++) a = fmaf(dr[k], wr[k], a);
            float sp = (a > 20.f) ? a : log1pf(expf(a));
            float u = sx[SXIDX(tok, e)];
            du[(size_t)(tok0+tok)*512 + e] = make_float2(sp, u);
        }
    }
}

// Selective scan: chunked register prefetch + pipelined shfl reduction
__global__ __launch_bounds__(256) void scan_kernel(const float2* __restrict__ du,
                            const float* __restrict__ xz,
                            const float2* __restrict__ bc,
                            const float* __restrict__ A_log,
                            const float* __restrict__ Dp,
                            float* __restrict__ yout)
{
    int tid = blockIdx.x * blockDim.x + threadIdx.x;
    int ch = tid >> 4;
    int n = tid & 15;
    int b = ch >> 9;
    int e = ch & 511;
    float A  = -expf(A_log[e*16 + n]);
    float Dv = Dp[e];
    const float2* duP = du + (size_t)(b*256)*512 + e;
    const float2* bcP = bc + (size_t)(b*256)*16 + n;
    const float*  zP  = xz + (size_t)(b*256)*1024 + 512 + e;
    float* yP = yout + (size_t)(b*256)*512 + e;

    float2 dv[2][8], bv[2][8];
    float  zv[2][8];
    #pragma unroll
    for (int i = 0; i < 8; i++) {
        dv[0][i] = duP[i*512];
        bv[0][i] = bcP[i*16];
    }
    if (n == 0) {
        #pragma unroll
        for (int i = 0; i < 8; i++) zv[0][i] = zP[i*1024];
    }
    float h = 0.f;
    int buf = 0;
    #pragma unroll 1
    for (int c = 0; c < 32; c++) {
        int nb = buf ^ 1;
        if (c < 31) {
            int t1 = c*8 + 8;
            #pragma unroll
            for (int i = 0; i < 8; i++) {
                dv[nb][i] = duP[(t1+i)*512];
                bv[nb][i] = bcP[(t1+i)*16];
            }
            if (n == 0) {
                #pragma unroll
                for (int i = 0; i < 8; i++) zv[nb][i] = zP[(size_t)(t1+i)*1024];
            }
        }
        float part[8];
        #pragma unroll
        for (int i = 0; i < 8; i++) {
            float2 duv = dv[buf][i];
            float2 bcv = bv[buf][i];
            float dA = __expf(duv.x * A);
            h = fmaf(h, dA, duv.x * bcv.x * duv.y);
            part[i] = h * bcv.y;
        }
        #pragma unroll
        for (int o = 8; o > 0; o >>= 1) {
            #pragma unroll
            for (int i = 0; i < 8; i++)
                part[i] += __shfl_down_sync(0xffffffffu, part[i], o, 16);
        }
        if (n == 0) {
            #pragma unroll
            for (int i = 0; i < 8; i++) {
                float z = zv[buf][i];
                float yy = part[i] + dv[buf][i].y * Dv;
                yP[(size_t)(c*8+i)*512] = yy * (z / (1.f + __expf(-z)));
            }
        }
        buf = nb;
    }
}

// =====================================================================
// Head tail
// =====================================================================
__global__ __launch_bounds__(256) void head2_kernel(const float* __restrict__ hh,
                             const float* __restrict__ w,
                             const float* __restrict__ b,
                             float* __restrict__ logits)
{
    int wid = (blockIdx.x * blockDim.x + threadIdx.x) >> 5;
    int lane = threadIdx.x & 31;
    const float* xr = hh + (size_t)wid*64;
    float acc = fmaf(xr[lane], w[lane], xr[lane+32]*w[lane+32]);
    #pragma unroll
    for (int o = 16; o > 0; o >>= 1) acc += __shfl_down_sync(0xffffffffu, acc, o);
    if (lane == 0) logits[wid] = acc + b[0];
}

__global__ __launch_bounds__(256) void softmax_kernel(const float* __restrict__ logits,
                               float* __restrict__ out)
{
    int b = blockIdx.x;
    int t = threadIdx.x;
    float v = logits[b*256 + t];
    __shared__ float red[8];
    __shared__ float sM, sS;
    float m = v;
    #pragma unroll
    for (int o = 16; o > 0; o >>= 1) m = fmaxf(m, __shfl_xor_sync(0xffffffffu, m, o));
    if ((t & 31) == 0) red[t >> 5] = m;
    __syncthreads();
    if (t < 8) {
        float mm = red[t];
        #pragma unroll
        for (int o = 4; o > 0; o >>= 1) mm = fmaxf(mm, __shfl_xor_sync(0xffu, mm, o, 8));
        if (t == 0) sM = mm;
    }
    __syncthreads();
    float e = expf(v - sM);
    float s = e;
    #pragma unroll
    for (int o = 16; o > 0; o >>= 1) s += __shfl_xor_sync(0xffffffffu, s, o);
    __syncthreads();
    if ((t & 31) == 0) red[t >> 5] = s;
    __syncthreads();
    if (t < 8) {
        float ss2 = red[t];
        #pragma unroll
        for (int o = 4; o > 0; o >>= 1) ss2 += __shfl_xor_sync(0xffu, ss2, o, 8);
        if (t == 0) sS = ss2;
    }
    __syncthreads();
    out[b*256 + t] = (t == 0) ? 0.f : e / sS;
}

// =====================================================================
// Launcher
// =====================================================================
extern "C" void kernel_launch(void* const* d_in, const int* in_sizes, int n_in,
                              void* d_out, int out_size)
{
    (void)in_sizes; (void)n_in; (void)out_size;
    const float* x        = (const float*)d_in[0];
    const float* cnn_w1   = (const float*)d_in[1];
    const float* cnn_b1   = (const float*)d_in[2];
    const float* cnn_w2   = (const float*)d_in[3];
    const float* cnn_b2   = (const float*)d_in[4];
    const float* cnn_w3   = (const float*)d_in[5];
    const float* cnn_b3   = (const float*)d_in[6];
    const float* fc_w     = (const float*)d_in[7];
    const float* fc_b     = (const float*)d_in[8];
    const float* norm_w   = (const float*)d_in[9];
    const float* in_proj_w= (const float*)d_in[10];
    const float* conv1d_w = (const float*)d_in[11];
    const float* conv1d_b = (const float*)d_in[12];
    const float* x_proj_w = (const float*)d_in[13];
    const float* dt_proj_w= (const float*)d_in[14];
    const float* dt_proj_b= (const float*)d_in[15];
    const float* A_log    = (const float*)d_in[16];
    const float* Dp       = (const float*)d_in[17];
    const float* out_proj_w=(const float*)d_in[18];
    const float* norm_f_w = (const float*)d_in[19];
    const float* head_w1  = (const float*)d_in[20];
    const float* head_b1  = (const float*)d_in[21];
    const float* head_w2  = (const float*)d_in[22];
    const float* head_b2  = (const float*)d_in[23];
    float* out = (float*)d_out;

    float *f1, *f2, *h, *xn, *xz, *y, *hh, *logits;
    float2 *bc, *du;
    cudaGetSymbolAddress((void**)&f1, g_f1);
    cudaGetSymbolAddress((void**)&f2, g_f2);
    cudaGetSymbolAddress((void**)&h,  g_h);
    cudaGetSymbolAddress((void**)&xn, g_xn);
    cudaGetSymbolAddress((void**)&xz, g_xz);
    cudaGetSymbolAddress((void**)&bc, g_bc);
    cudaGetSymbolAddress((void**)&du, g_du);
    cudaGetSymbolAddress((void**)&y,  g_y);
    cudaGetSymbolAddress((void**)&hh, g_hh);
    cudaGetSymbolAddress((void**)&logits, g_logits);

    // --- CNN encoder ---
    conv1_kernel<<<2048, 512>>>(x, cnn_w1, cnn_b1, f1);
    conv2_kernel<<<2048, 256>>>(f1, cnn_w2, cnn_b2, f2);
    conv3poolfc_kernel<<<1024, 256>>>(f2, cnn_w3, cnn_b3, fc_w, fc_b, h);

    // --- Mamba layers ---
    for (int l = 0; l < 6; l++) {
        const float* nw  = norm_w     + (size_t)l*DM;
        const float* ipw = in_proj_w  + (size_t)l*2*DI*DM;
        const float* cw  = conv1d_w   + (size_t)l*DI*4;
        const float* cb  = conv1d_b   + (size_t)l*DI;
        const float* xpw = x_proj_w   + (size_t)l*48*DI;
        const float* dpw = dt_proj_w  + (size_t)l*DI*DTR;
        const float* dpb = dt_proj_b  + (size_t)l*DI;
        const float* al  = A_log      + (size_t)l*DI*DS;
        const float* dv  = Dp         + (size_t)l*DI;
        const float* opw = out_proj_w + (size_t)l*DM*DI;

        rmsnorm_kernel<<<256, 256>>>(h, nw, xn);
        gemm64_kernel<<<dim3(16, 32), 256>>>(xn, ipw, xz, BT, 1024, 256);
        xproj_fused_kernel<<<128, 256>>>(xz, cw, cb, xpw, dpw, dpb, bc, du);
        scan_kernel<<<BATCH*DI*DS/256, 256>>>(du, xz, bc, al, dv, y);
        gemm32x64_kernel<1><<<dim3(4, 64), 256>>>(y, opw, nullptr, h, BT, 256, 512);
    }

    // --- Head ---
    rmsnorm_kernel<<<256, 256>>>(h, norm_f_w, xn);
    gemm32x64_kernel<2><<<dim3(1, 64), 256>>>(xn, head_w1, head_b1, hh, BT, 64, 256);
    head2_kernel<<<BT*32/256, 256>>>(hh, head_w2, head_b2, logits);
    softmax_kernel<<<BATCH, 256>>>(logits, out);
}